// round 2
// baseline (speedup 1.0000x reference)
#include <cuda_runtime.h>
#include <math.h>

// Problem constants
#define Bb  4
#define Aa  3
#define Ss  1024
#define Hh  768
#define NHh 12
#define HDd 64

// Device scratch (allocation-free rule: __device__ globals)
__device__ float g_Q  [Bb*Ss*Hh];          // Q projection  [B,S,NH,HD]
__device__ float g_K  [Bb*Aa*Ss*Hh];       // K projection  [B,A,S,NH,HD]
__device__ float g_V  [Bb*Aa*Ss*Hh];       // V projection  [B,A,S,NH,HD]
__device__ float g_att[Bb*Ss*Hh];          // attended      [B,S,NH,HD]
__device__ float g_O  [Bb*Ss*Hh];          // pre-LN (proj + residual)

// ---------------------------------------------------------------------------
// GEMM: out[m,n] = sum_k X[m,k]*W[n,k] + bias[n] (+ res[m,n] if ADD)
// BM=BN=128, BK=16, 256 threads, 8x8 register tile per thread.
// M % 128 == 0, N % 128 == 0, K % 16 == 0 (all true for this problem).
// ---------------------------------------------------------------------------
template<bool ADD>
__global__ __launch_bounds__(256)
void gemm_bias(const float* __restrict__ X, const float* __restrict__ W,
               const float* __restrict__ bias, const float* __restrict__ res,
               float* __restrict__ out, int M, int N, int K)
{
    const int BM = 128, BN = 128, BK = 16;
    __shared__ float Xs[BK][BM + 4];
    __shared__ float Ws[BK][BN + 4];

    const int m0 = blockIdx.y * BM;
    const int n0 = blockIdx.x * BN;
    const int tid = threadIdx.x;
    const int tx = tid & 15;   // n block: tx*8 .. tx*8+7
    const int ty = tid >> 4;   // m block: ty*8 .. ty*8+7

    float acc[8][8];
#pragma unroll
    for (int i = 0; i < 8; i++)
#pragma unroll
        for (int j = 0; j < 8; j++) acc[i][j] = 0.f;

    for (int k0 = 0; k0 < K; k0 += BK) {
        // cooperative loads: each thread 2x float4 from X and W
#pragma unroll
        for (int p = 0; p < 2; p++) {
            int r = (tid >> 2) + p * 64;     // row within tile (0..127)
            int c = (tid & 3) * 4;           // k within tile   (0..12)
            float4 xv = *(const float4*)(X + (size_t)(m0 + r) * K + k0 + c);
            Xs[c + 0][r] = xv.x; Xs[c + 1][r] = xv.y;
            Xs[c + 2][r] = xv.z; Xs[c + 3][r] = xv.w;
            float4 wv = *(const float4*)(W + (size_t)(n0 + r) * K + k0 + c);
            Ws[c + 0][r] = wv.x; Ws[c + 1][r] = wv.y;
            Ws[c + 2][r] = wv.z; Ws[c + 3][r] = wv.w;
        }
        __syncthreads();

#pragma unroll
        for (int k = 0; k < BK; k++) {
            float4 a0 = *(float4*)&Xs[k][ty * 8];
            float4 a1 = *(float4*)&Xs[k][ty * 8 + 4];
            float4 b0 = *(float4*)&Ws[k][tx * 8];
            float4 b1 = *(float4*)&Ws[k][tx * 8 + 4];
            float a[8] = {a0.x, a0.y, a0.z, a0.w, a1.x, a1.y, a1.z, a1.w};
            float bb[8] = {b0.x, b0.y, b0.z, b0.w, b1.x, b1.y, b1.z, b1.w};
#pragma unroll
            for (int i = 0; i < 8; i++)
#pragma unroll
                for (int j = 0; j < 8; j++)
                    acc[i][j] += a[i] * bb[j];
        }
        __syncthreads();
    }

    // epilogue
#pragma unroll
    for (int i = 0; i < 8; i++) {
        int m = m0 + ty * 8 + i;
#pragma unroll
        for (int j = 0; j < 8; j += 4) {
            int n = n0 + tx * 8 + j;
            float4 o;
            o.x = acc[i][j + 0] + bias[n + 0];
            o.y = acc[i][j + 1] + bias[n + 1];
            o.z = acc[i][j + 2] + bias[n + 2];
            o.w = acc[i][j + 3] + bias[n + 3];
            if (ADD) {
                float4 rr = *(const float4*)(res + (size_t)m * N + n);
                o.x += rr.x; o.y += rr.y; o.z += rr.z; o.w += rr.w;
            }
            *(float4*)(out + (size_t)m * N + n) = o;
        }
    }
}

// ---------------------------------------------------------------------------
// Attention: per (b,h,q-tile of 32), stream 32-key chunks.
//   scores[q, a, s] = (Q[q,:] . K[a,s,:]) / 8
//   p[a] = softmax over a (3 adapters) per (q,s); O[q,:] += sum_{a,s} p * V[a,s,:]
// K and V share one smem buffer (V loaded after scores are consumed).
// Static smem = 47.5KB < 48KB.
// ---------------------------------------------------------------------------
__global__ __launch_bounds__(256)
void attn_kernel(const float* __restrict__ Q, const float* __restrict__ K,
                 const float* __restrict__ V, float* __restrict__ O)
{
    const int TQ = 32, TS = 32;
    __shared__ float Qs [TQ][HDd + 4];        //  8704 B
    __shared__ float KVs[Aa * TS][HDd + 4];   // 26112 B
    __shared__ float Ps [Aa][TQ][TS + 1];     // 12672 B

    const int q0 = blockIdx.x * TQ;
    const int h  = blockIdx.y;
    const int b  = blockIdx.z;
    const int tid = threadIdx.x;
    const int tx = tid & 15;   // s-pairs for scores / d-quad for PV
    const int ty = tid >> 4;   // q-pairs

    // Load Q tile: 32 rows x 64 floats
    for (int i = tid; i < TQ * 16; i += 256) {
        int q = i >> 4;
        int c = (i & 15) * 4;
        *(float4*)&Qs[q][c] =
            *(const float4*)(Q + (((size_t)(b * Ss + q0 + q) * NHh + h) << 6) + c);
    }

    float o[2][4];
#pragma unroll
    for (int qi = 0; qi < 2; qi++)
#pragma unroll
        for (int j = 0; j < 4; j++) o[qi][j] = 0.f;

    for (int s0 = 0; s0 < Ss; s0 += TS) {
        __syncthreads();  // previous PV done (also covers Q-tile on iter 0)

        // Load K chunk: 3 adapters x 32 keys x 64 floats
        for (int i = tid; i < Aa * TS * 16; i += 256) {
            int r = i >> 4;
            int c = (i & 15) * 4;
            int a = r / TS, s = r % TS;
            size_t base = ((size_t)((b * Aa + a) * Ss + s0 + s)) * Hh + h * HDd + c;
            *(float4*)&KVs[r][c] = *(const float4*)(K + base);
        }
        __syncthreads();

        // Scores: each thread computes z[a][2q][2s]
        float z[3][2][2];
#pragma unroll
        for (int a = 0; a < 3; a++)
#pragma unroll
            for (int i = 0; i < 2; i++)
#pragma unroll
                for (int j = 0; j < 2; j++) z[a][i][j] = 0.f;

#pragma unroll 4
        for (int d4 = 0; d4 < 16; d4++) {
            float4 qa = *(float4*)&Qs[ty][d4 * 4];
            float4 qb = *(float4*)&Qs[ty + 16][d4 * 4];
#pragma unroll
            for (int a = 0; a < 3; a++) {
                float4 ka = *(float4*)&KVs[a * TS + tx][d4 * 4];
                float4 kb = *(float4*)&KVs[a * TS + tx + 16][d4 * 4];
                z[a][0][0] += qa.x*ka.x + qa.y*ka.y + qa.z*ka.z + qa.w*ka.w;
                z[a][0][1] += qa.x*kb.x + qa.y*kb.y + qa.z*kb.z + qa.w*kb.w;
                z[a][1][0] += qb.x*ka.x + qb.y*ka.y + qb.z*ka.z + qb.w*ka.w;
                z[a][1][1] += qb.x*kb.x + qb.y*kb.y + qb.z*kb.z + qb.w*kb.w;
            }
        }
        __syncthreads();  // everyone done reading K before V overwrites it

        // Softmax over adapters, write P; concurrently load V into KVs
#pragma unroll
        for (int qi = 0; qi < 2; qi++)
#pragma unroll
            for (int si = 0; si < 2; si++) {
                float z0 = z[0][qi][si] * 0.125f;
                float z1 = z[1][qi][si] * 0.125f;
                float z2 = z[2][qi][si] * 0.125f;
                float m  = fmaxf(z0, fmaxf(z1, z2));
                float e0 = __expf(z0 - m);
                float e1 = __expf(z1 - m);
                float e2 = __expf(z2 - m);
                float inv = 1.f / (e0 + e1 + e2);
                int q = ty + qi * 16, s = tx + si * 16;
                Ps[0][q][s] = e0 * inv;
                Ps[1][q][s] = e1 * inv;
                Ps[2][q][s] = e2 * inv;
            }

        for (int i = tid; i < Aa * TS * 16; i += 256) {
            int r = i >> 4;
            int c = (i & 15) * 4;
            int a = r / TS, s = r % TS;
            size_t base = ((size_t)((b * Aa + a) * Ss + s0 + s)) * Hh + h * HDd + c;
            *(float4*)&KVs[r][c] = *(const float4*)(V + base);
        }
        __syncthreads();

        // PV: O[q, d] += sum_n P[n, q] * V[n, d]
#pragma unroll 8
        for (int n = 0; n < Aa * TS; n++) {
            int a = n >> 5, s = n & 31;
            float p0 = Ps[a][ty][s];
            float p1 = Ps[a][ty + 16][s];
            float4 v = *(float4*)&KVs[n][tx * 4];
            o[0][0] += p0 * v.x; o[0][1] += p0 * v.y;
            o[0][2] += p0 * v.z; o[0][3] += p0 * v.w;
            o[1][0] += p1 * v.x; o[1][1] += p1 * v.y;
            o[1][2] += p1 * v.z; o[1][3] += p1 * v.w;
        }
    }

    // Write attended [B,S,NH,HD]
#pragma unroll
    for (int qi = 0; qi < 2; qi++) {
        int q = ty + qi * 16;
        float4 v = make_float4(o[qi][0], o[qi][1], o[qi][2], o[qi][3]);
        *(float4*)(O + (((size_t)(b * Ss + q0 + q) * NHh + h) << 6) + tx * 4) = v;
    }
}

// ---------------------------------------------------------------------------
// Row LayerNorm over H=768 (one block per row, 256 threads x 3 elements)
// ---------------------------------------------------------------------------
__global__ __launch_bounds__(256)
void ln_kernel(const float* __restrict__ X, const float* __restrict__ gamma,
               const float* __restrict__ beta, float* __restrict__ out)
{
    __shared__ float red[256];
    const int row = blockIdx.x;
    const int tid = threadIdx.x;
    const float* x = X + (size_t)row * Hh;

    float vals[3];
    float s = 0.f;
#pragma unroll
    for (int i = 0; i < 3; i++) {
        vals[i] = x[tid + i * 256];
        s += vals[i];
    }
    red[tid] = s;
    __syncthreads();
#pragma unroll
    for (int off = 128; off > 0; off >>= 1) {
        if (tid < off) red[tid] += red[tid + off];
        __syncthreads();
    }
    float mean = red[0] * (1.f / Hh);
    __syncthreads();

    float v = 0.f;
#pragma unroll
    for (int i = 0; i < 3; i++) {
        float d = vals[i] - mean;
        v += d * d;
    }
    red[tid] = v;
    __syncthreads();
#pragma unroll
    for (int off = 128; off > 0; off >>= 1) {
        if (tid < off) red[tid] += red[tid + off];
        __syncthreads();
    }
    float inv = rsqrtf(red[0] * (1.f / Hh) + 1e-5f);

#pragma unroll
    for (int i = 0; i < 3; i++) {
        int c = tid + i * 256;
        out[(size_t)row * Hh + c] = (vals[i] - mean) * inv * gamma[c] + beta[c];
    }
}

// Constant fill (avg_weights == 1/3 analytically: softmax over the adapter
// axis sums to 1 for every (b,h,q,s), so mean over heads then adapters = 1/A)
__global__ void fill_kernel(float* __restrict__ p, int n4, float v)
{
    int i = blockIdx.x * blockDim.x + threadIdx.x;
    if (i < n4) {
        float4 f = make_float4(v, v, v, v);
        *(float4*)(p + (size_t)i * 4) = f;
    }
}

// ---------------------------------------------------------------------------
extern "C" void kernel_launch(void* const* d_in, const int* in_sizes, int n_in,
                              void* d_out, int out_size)
{
    const float* query = (const float*)d_in[0];
    const float* adap  = (const float*)d_in[1];
    const float* Wq = (const float*)d_in[2];  const float* bq = (const float*)d_in[3];
    const float* Wk = (const float*)d_in[4];  const float* bk = (const float*)d_in[5];
    const float* Wv = (const float*)d_in[6];  const float* bv = (const float*)d_in[7];
    const float* Wo = (const float*)d_in[8];  const float* bo = (const float*)d_in[9];
    const float* gamma = (const float*)d_in[10];
    const float* beta  = (const float*)d_in[11];
    float* out = (float*)d_out;

    float *Qp, *Kp, *Vp, *Att, *Oo;
    cudaGetSymbolAddress((void**)&Qp,  g_Q);
    cudaGetSymbolAddress((void**)&Kp,  g_K);
    cudaGetSymbolAddress((void**)&Vp,  g_V);
    cudaGetSymbolAddress((void**)&Att, g_att);
    cudaGetSymbolAddress((void**)&Oo,  g_O);

    const int MQ = Bb * Ss;            // 4096
    const int MKV = Bb * Aa * Ss;      // 12288

    dim3 blk(256);
    dim3 gq(Hh / 128, MQ / 128);       // (6, 32)
    dim3 gkv(Hh / 128, MKV / 128);     // (6, 96)

    // Projections
    gemm_bias<false><<<gq,  blk>>>(query, Wq, bq, nullptr, Qp, MQ,  Hh, Hh);
    gemm_bias<false><<<gkv, blk>>>(adap,  Wk, bk, nullptr, Kp, MKV, Hh, Hh);
    gemm_bias<false><<<gkv, blk>>>(adap,  Wv, bv, nullptr, Vp, MKV, Hh, Hh);

    // Attention
    dim3 ga(Ss / 32, NHh, Bb);         // (32, 12, 4)
    attn_kernel<<<ga, blk>>>(Qp, Kp, Vp, Att);

    // Output projection + residual
    gemm_bias<true><<<gq, blk>>>(Att, Wo, bo, query, Oo, MQ, Hh, Hh);

    // LayerNorm into first output region
    ln_kernel<<<MQ, blk>>>(Oo, gamma, beta, out);

    // avg_weights region = constant 1/3
    const int out0 = Bb * Ss * Hh;              // 3,145,728
    const int navg = out_size - out0;           // 4,194,304
    int n4 = navg / 4;
    fill_kernel<<<(n4 + 255) / 256, 256>>>(out + out0, n4, 1.0f / 3.0f);
}

// round 3
// speedup vs baseline: 1.2465x; 1.2465x over previous
#include <cuda_runtime.h>
#include <math.h>

// Problem constants
#define Bb  4
#define Aa  3
#define Ss  1024
#define Hh  768
#define NHh 12
#define HDd 64

// Device scratch (allocation-free rule: __device__ globals)
__device__ float g_Q  [Bb*Ss*Hh];          // Q projection  [B,S,NH,HD]
__device__ float g_K  [Bb*Aa*Ss*Hh];       // K projection  [B,A,S,NH,HD]
__device__ float g_V  [Bb*Aa*Ss*Hh];       // V projection  [B,A,S,NH,HD]
__device__ float g_att[Bb*Ss*Hh];          // attended      [B,S,NH,HD]
__device__ float g_O  [Bb*Ss*Hh];          // pre-LN (proj + residual)

// ---------------------------------------------------------------------------
// GEMM: out[m,n] = sum_k X[m,k]*W[n,k] + bias[n] (+ res[m,n] if ADD)
// BM=BN=128, BK=16, 256 threads, 8x8 register tile per thread.
// ---------------------------------------------------------------------------
template<bool ADD>
__global__ __launch_bounds__(256)
void gemm_bias(const float* __restrict__ X, const float* __restrict__ W,
               const float* __restrict__ bias, const float* __restrict__ res,
               float* __restrict__ out, int M, int N, int K)
{
    const int BM = 128, BN = 128, BK = 16;
    __shared__ float Xs[BK][BM + 4];
    __shared__ float Ws[BK][BN + 4];

    const int m0 = blockIdx.y * BM;
    const int n0 = blockIdx.x * BN;
    const int tid = threadIdx.x;
    const int tx = tid & 15;
    const int ty = tid >> 4;

    float acc[8][8];
#pragma unroll
    for (int i = 0; i < 8; i++)
#pragma unroll
        for (int j = 0; j < 8; j++) acc[i][j] = 0.f;

    for (int k0 = 0; k0 < K; k0 += BK) {
#pragma unroll
        for (int p = 0; p < 2; p++) {
            int r = (tid >> 2) + p * 64;
            int c = (tid & 3) * 4;
            float4 xv = *(const float4*)(X + (size_t)(m0 + r) * K + k0 + c);
            Xs[c + 0][r] = xv.x; Xs[c + 1][r] = xv.y;
            Xs[c + 2][r] = xv.z; Xs[c + 3][r] = xv.w;
            float4 wv = *(const float4*)(W + (size_t)(n0 + r) * K + k0 + c);
            Ws[c + 0][r] = wv.x; Ws[c + 1][r] = wv.y;
            Ws[c + 2][r] = wv.z; Ws[c + 3][r] = wv.w;
        }
        __syncthreads();

#pragma unroll
        for (int k = 0; k < BK; k++) {
            float4 a0 = *(float4*)&Xs[k][ty * 8];
            float4 a1 = *(float4*)&Xs[k][ty * 8 + 4];
            float4 b0 = *(float4*)&Ws[k][tx * 8];
            float4 b1 = *(float4*)&Ws[k][tx * 8 + 4];
            float a[8] = {a0.x, a0.y, a0.z, a0.w, a1.x, a1.y, a1.z, a1.w};
            float bb[8] = {b0.x, b0.y, b0.z, b0.w, b1.x, b1.y, b1.z, b1.w};
#pragma unroll
            for (int i = 0; i < 8; i++)
#pragma unroll
                for (int j = 0; j < 8; j++)
                    acc[i][j] += a[i] * bb[j];
        }
        __syncthreads();
    }

#pragma unroll
    for (int i = 0; i < 8; i++) {
        int m = m0 + ty * 8 + i;
#pragma unroll
        for (int j = 0; j < 8; j += 4) {
            int n = n0 + tx * 8 + j;
            float4 o;
            o.x = acc[i][j + 0] + bias[n + 0];
            o.y = acc[i][j + 1] + bias[n + 1];
            o.z = acc[i][j + 2] + bias[n + 2];
            o.w = acc[i][j + 3] + bias[n + 3];
            if (ADD) {
                float4 rr = *(const float4*)(res + (size_t)m * N + n);
                o.x += rr.x; o.y += rr.y; o.z += rr.z; o.w += rr.w;
            }
            *(float4*)(out + (size_t)m * N + n) = o;
        }
    }
}

// ---------------------------------------------------------------------------
// Attention v2 — broadcast-heavy micro-tiles, softmax fully in registers.
//
// Block: 64 q-rows of one (b,h). 256 threads = 8 warps.
// Thread (ty = warp 0..7, tx = lane 0..31) owns:
//   scores: q = ty*8 .. ty*8+7  (8 rows), s = tx (one key position), all 3 adapters
//   PV:     q = ty*8 .. ty*8+7, d = tx*2, tx*2+1
//
// Per 32-key iteration:
//   scores (z[3][8]) -> register softmax over adapters -> STS.128 P -> PV.
// All LDS is either warp-broadcast (Q rows, P rows) or conflict-free
// lane-strided (pitch 68 floats => 4-bank stride per lane across 8-lane
// LDS.128 phases).
// smem = (64 + 96 + 96) * 68 floats = 69,632 B (dynamic) -> 3 blocks/SM.
// ---------------------------------------------------------------------------
#define PITCH 68

__global__ __launch_bounds__(256, 3)
void attn2_kernel(const float* __restrict__ Q, const float* __restrict__ K,
                  const float* __restrict__ V, float* __restrict__ O)
{
    extern __shared__ float sm[];
    float* Qs = sm;                    // [64][PITCH]
    float* KV = sm + 64 * PITCH;       // [96][PITCH]   K, then reused for V
    float* Ps = KV + 96 * PITCH;       // [96][PITCH]   P[n][q]

    const int q0 = blockIdx.x * 64;
    const int h  = blockIdx.y;
    const int b  = blockIdx.z;
    const int tid = threadIdx.x;
    const int tx = tid & 31;
    const int ty = tid >> 5;

    // Load Q tile (64 rows x 64 floats)
    for (int i = tid; i < 64 * 16; i += 256) {
        int q = i >> 4, c = (i & 15) * 4;
        *(float4*)&Qs[q * PITCH + c] =
            *(const float4*)(Q + (((size_t)((b * Ss + q0 + q) * NHh + h)) << 6) + c);
    }

    float2 o[8];
#pragma unroll
    for (int i = 0; i < 8; i++) o[i] = make_float2(0.f, 0.f);

    const size_t kvHead = (size_t)h * HDd;

    for (int s0 = 0; s0 < Ss; s0 += 32) {
        __syncthreads();   // prior PV finished (covers Q load on iter 0)

        // Load K chunk: rows n = a*32+s, 64 floats each
        for (int i = tid; i < 96 * 16; i += 256) {
            int r = i >> 4, c = (i & 15) * 4;
            int a = r >> 5, s = r & 31;
            size_t base = ((size_t)((b * Aa + a) * Ss + s0 + s)) * Hh + kvHead + c;
            *(float4*)&KV[r * PITCH + c] = *(const float4*)(K + base);
        }
        __syncthreads();

        // Scores: z[a][i] = Q[q=ty*8+i] . K[a, s=tx]
        float z[3][8];
#pragma unroll
        for (int a = 0; a < 3; a++)
#pragma unroll
            for (int i = 0; i < 8; i++) z[a][i] = 0.f;

#pragma unroll 4
        for (int d4 = 0; d4 < 16; d4++) {
            float4 k0 = *(float4*)&KV[(0 * 32 + tx) * PITCH + d4 * 4];
            float4 k1 = *(float4*)&KV[(1 * 32 + tx) * PITCH + d4 * 4];
            float4 k2 = *(float4*)&KV[(2 * 32 + tx) * PITCH + d4 * 4];
#pragma unroll
            for (int i = 0; i < 8; i++) {
                float4 qv = *(float4*)&Qs[(ty * 8 + i) * PITCH + d4 * 4];
                z[0][i] += qv.x*k0.x + qv.y*k0.y + qv.z*k0.z + qv.w*k0.w;
                z[1][i] += qv.x*k1.x + qv.y*k1.y + qv.z*k1.z + qv.w*k1.w;
                z[2][i] += qv.x*k2.x + qv.y*k2.y + qv.z*k2.z + qv.w*k2.w;
            }
        }
        __syncthreads();   // everyone done reading K before V overwrites it

        // Softmax over adapters — all in registers (reuse z as p)
#pragma unroll
        for (int i = 0; i < 8; i++) {
            float z0 = z[0][i] * 0.125f;
            float z1 = z[1][i] * 0.125f;
            float z2 = z[2][i] * 0.125f;
            float m  = fmaxf(z0, fmaxf(z1, z2));
            float e0 = __expf(z0 - m);
            float e1 = __expf(z1 - m);
            float e2 = __expf(z2 - m);
            float inv = 1.f / (e0 + e1 + e2);
            z[0][i] = e0 * inv;
            z[1][i] = e1 * inv;
            z[2][i] = e2 * inv;
        }

        // Write P[n][q] (conflict-free STS.128: lane row stride = PITCH)
#pragma unroll
        for (int a = 0; a < 3; a++) {
            float4 pa = make_float4(z[a][0], z[a][1], z[a][2], z[a][3]);
            float4 pb = make_float4(z[a][4], z[a][5], z[a][6], z[a][7]);
            *(float4*)&Ps[(a * 32 + tx) * PITCH + ty * 8]     = pa;
            *(float4*)&Ps[(a * 32 + tx) * PITCH + ty * 8 + 4] = pb;
        }

        // Load V chunk into KV
        for (int i = tid; i < 96 * 16; i += 256) {
            int r = i >> 4, c = (i & 15) * 4;
            int a = r >> 5, s = r & 31;
            size_t base = ((size_t)((b * Aa + a) * Ss + s0 + s)) * Hh + kvHead + c;
            *(float4*)&KV[r * PITCH + c] = *(const float4*)(V + base);
        }
        __syncthreads();

        // PV: o[q][d] += sum_n P[n][q] * V[n][d]
#pragma unroll 8
        for (int n = 0; n < 96; n++) {
            float4 pA = *(float4*)&Ps[n * PITCH + ty * 8];
            float4 pB = *(float4*)&Ps[n * PITCH + ty * 8 + 4];
            float2 v  = *(float2*)&KV[n * PITCH + tx * 2];
            o[0].x += pA.x * v.x;  o[0].y += pA.x * v.y;
            o[1].x += pA.y * v.x;  o[1].y += pA.y * v.y;
            o[2].x += pA.z * v.x;  o[2].y += pA.z * v.y;
            o[3].x += pA.w * v.x;  o[3].y += pA.w * v.y;
            o[4].x += pB.x * v.x;  o[4].y += pB.x * v.y;
            o[5].x += pB.y * v.x;  o[5].y += pB.y * v.y;
            o[6].x += pB.z * v.x;  o[6].y += pB.z * v.y;
            o[7].x += pB.w * v.x;  o[7].y += pB.w * v.y;
        }
    }

    // Write attended [B,S,NH,HD]
#pragma unroll
    for (int i = 0; i < 8; i++) {
        int q = q0 + ty * 8 + i;
        *(float2*)(O + (((size_t)((b * Ss + q) * NHh + h)) << 6) + tx * 2) = o[i];
    }
}

// ---------------------------------------------------------------------------
// Row LayerNorm over H=768 (one block per row, 256 threads x 3 elements)
// ---------------------------------------------------------------------------
__global__ __launch_bounds__(256)
void ln_kernel(const float* __restrict__ X, const float* __restrict__ gamma,
               const float* __restrict__ beta, float* __restrict__ out)
{
    __shared__ float red[256];
    const int row = blockIdx.x;
    const int tid = threadIdx.x;
    const float* x = X + (size_t)row * Hh;

    float vals[3];
    float s = 0.f;
#pragma unroll
    for (int i = 0; i < 3; i++) {
        vals[i] = x[tid + i * 256];
        s += vals[i];
    }
    red[tid] = s;
    __syncthreads();
#pragma unroll
    for (int off = 128; off > 0; off >>= 1) {
        if (tid < off) red[tid] += red[tid + off];
        __syncthreads();
    }
    float mean = red[0] * (1.f / Hh);
    __syncthreads();

    float v = 0.f;
#pragma unroll
    for (int i = 0; i < 3; i++) {
        float d = vals[i] - mean;
        v += d * d;
    }
    red[tid] = v;
    __syncthreads();
#pragma unroll
    for (int off = 128; off > 0; off >>= 1) {
        if (tid < off) red[tid] += red[tid + off];
        __syncthreads();
    }
    float inv = rsqrtf(red[0] * (1.f / Hh) + 1e-5f);

#pragma unroll
    for (int i = 0; i < 3; i++) {
        int c = tid + i * 256;
        out[(size_t)row * Hh + c] = (vals[i] - mean) * inv * gamma[c] + beta[c];
    }
}

// Constant fill (avg_weights == 1/3 analytically: softmax over the adapter
// axis sums to 1 for every (b,h,q,s), so mean over heads then adapters = 1/A)
__global__ void fill_kernel(float* __restrict__ p, int n4, float v)
{
    int i = blockIdx.x * blockDim.x + threadIdx.x;
    if (i < n4) {
        float4 f = make_float4(v, v, v, v);
        *(float4*)(p + (size_t)i * 4) = f;
    }
}

// ---------------------------------------------------------------------------
extern "C" void kernel_launch(void* const* d_in, const int* in_sizes, int n_in,
                              void* d_out, int out_size)
{
    const float* query = (const float*)d_in[0];
    const float* adap  = (const float*)d_in[1];
    const float* Wq = (const float*)d_in[2];  const float* bq = (const float*)d_in[3];
    const float* Wk = (const float*)d_in[4];  const float* bk = (const float*)d_in[5];
    const float* Wv = (const float*)d_in[6];  const float* bv = (const float*)d_in[7];
    const float* Wo = (const float*)d_in[8];  const float* bo = (const float*)d_in[9];
    const float* gamma = (const float*)d_in[10];
    const float* beta  = (const float*)d_in[11];
    float* out = (float*)d_out;

    float *Qp, *Kp, *Vp, *Att, *Oo;
    cudaGetSymbolAddress((void**)&Qp,  g_Q);
    cudaGetSymbolAddress((void**)&Kp,  g_K);
    cudaGetSymbolAddress((void**)&Vp,  g_V);
    cudaGetSymbolAddress((void**)&Att, g_att);
    cudaGetSymbolAddress((void**)&Oo,  g_O);

    const int MQ = Bb * Ss;            // 4096
    const int MKV = Bb * Aa * Ss;      // 12288

    dim3 blk(256);
    dim3 gq(Hh / 128, MQ / 128);       // (6, 32)
    dim3 gkv(Hh / 128, MKV / 128);     // (6, 96)

    // Projections
    gemm_bias<false><<<gq,  blk>>>(query, Wq, bq, nullptr, Qp, MQ,  Hh, Hh);
    gemm_bias<false><<<gkv, blk>>>(adap,  Wk, bk, nullptr, Kp, MKV, Hh, Hh);
    gemm_bias<false><<<gkv, blk>>>(adap,  Wv, bv, nullptr, Vp, MKV, Hh, Hh);

    // Attention (dynamic smem 69,632 B -> needs opt-in above 48KB)
    const int smemBytes = (64 + 96 + 96) * PITCH * (int)sizeof(float);
    cudaFuncSetAttribute(attn2_kernel,
                         cudaFuncAttributeMaxDynamicSharedMemorySize, smemBytes);
    dim3 ga(Ss / 64, NHh, Bb);         // (16, 12, 4)
    attn2_kernel<<<ga, blk, smemBytes>>>(Qp, Kp, Vp, Att);

    // Output projection + residual
    gemm_bias<true><<<gq, blk>>>(Att, Wo, bo, query, Oo, MQ, Hh, Hh);

    // LayerNorm into first output region
    ln_kernel<<<MQ, blk>>>(Oo, gamma, beta, out);

    // avg_weights region = constant 1/3
    const int out0 = Bb * Ss * Hh;
    const int navg = out_size - out0;
    int n4 = navg / 4;
    fill_kernel<<<(n4 + 255) / 256, 256>>>(out + out0, n4, 1.0f / 3.0f);
}